// round 14
// baseline (speedup 1.0000x reference)
#include <cuda_runtime.h>
#include <cuda_bf16.h>
#include <cuda_fp16.h>

#define BB 64
#define SSEQ 440
#define DDIM 256
#define HN 8
#define FFD 512
#define LNUM 6
#define BS_ (BB*SSEQ)   // 28160

// ------------ static device scratch (no allocation) ------------
__device__ float g_h[(size_t)BS_*DDIM];
__device__ float g_qkv[(size_t)BS_*3*DDIM];   // holds __half when QKV gemm writes half
__device__ float g_t1[(size_t)BS_*FFD];
__device__ float g_t2[(size_t)BS_*DDIM];

__device__ __forceinline__ void mma_f16_k16(float& c0, float& c1, float& c2, float& c3,
                                            unsigned a0, unsigned a1, unsigned a2, unsigned a3,
                                            unsigned b0, unsigned b1)
{
    asm volatile(
        "mma.sync.aligned.m16n8k16.row.col.f32.f16.f16.f32 "
        "{%0,%1,%2,%3}, {%4,%5,%6,%7}, {%8,%9}, {%0,%1,%2,%3};"
        : "+f"(c0), "+f"(c1), "+f"(c2), "+f"(c3)
        : "r"(a0), "r"(a1), "r"(a2), "r"(a3), "r"(b0), "r"(b1));
}

__device__ __forceinline__ void mma_f16_k8(float& c0, float& c1, float& c2, float& c3,
                                           unsigned a0, unsigned a1, unsigned b0)
{
    asm volatile(
        "mma.sync.aligned.m16n8k8.row.col.f32.f16.f16.f32 "
        "{%0,%1,%2,%3}, {%4,%5}, {%6}, {%0,%1,%2,%3};"
        : "+f"(c0), "+f"(c1), "+f"(c2), "+f"(c3)
        : "r"(a0), "r"(a1), "r"(b0));
}

__device__ __forceinline__ unsigned packh2(float a, float b) {
    __half2 h = __floats2half2_rn(a, b);
    return *(unsigned*)&h;
}

__device__ __forceinline__ unsigned ex2h2(unsigned s) {
    unsigned d;
    asm("ex2.approx.f16x2 %0, %1;" : "=r"(d) : "r"(s));
    return d;
}

// ------------------------ embedding ------------------------
__global__ void k_embed(const int* __restrict__ x,
                        const float* __restrict__ ev, const float* __restrict__ px,
                        const float* __restrict__ py, const float* __restrict__ st,
                        const int* __restrict__ tkx, const int* __restrict__ tky,
                        const int* __restrict__ tks)
{
    int bs = blockIdx.x;
    int s = bs % SSEQ;
    int d = threadIdx.x;
    int xi = x[bs];
    g_h[(size_t)bs*DDIM + d] =
        ev[xi*DDIM + d] + px[tkx[s]*DDIM + d] + py[tky[s]*DDIM + d] + st[tks[s]*DDIM + d];
}

// ---- FP16 tensor-core GEMM; optional fp16 output ----
__global__ __launch_bounds__(256, 2) void k_gemm(
    const float* __restrict__ A, const float* __restrict__ W,
    const float* __restrict__ bias, float* __restrict__ C,
    int M, int N, int K, int relu, int outHalf)
{
    __shared__ unsigned As[128][12];
    __shared__ unsigned Bs[128][12];
    int tid = threadIdx.x;
    int bm = blockIdx.y * 128, bn = blockIdx.x * 128;
    int row = tid >> 1, wq = (tid & 1) * 4;
    const float* Ap = A + (size_t)(bm + row) * K + (tid & 1) * 8;
    const float* Wp = W + (size_t)(bn + row) * K + (tid & 1) * 8;
    float4 pa0 = *(const float4*)Ap;
    float4 pa1 = *(const float4*)(Ap + 4);
    float4 pb0 = *(const float4*)Wp;
    float4 pb1 = *(const float4*)(Wp + 4);

    int lane = tid & 31, warp = tid >> 5;
    int wm = (warp & 1) * 64, wn = (warp >> 1) * 32;
    int grp = lane >> 2, qd = lane & 3;

    float c[4][4][4];
#pragma unroll
    for (int mt = 0; mt < 4; mt++)
#pragma unroll
        for (int nt = 0; nt < 4; nt++)
#pragma unroll
            for (int r = 0; r < 4; r++) c[mt][nt][r] = 0.f;

    int nk = K >> 4;
    for (int kt = 0; kt < nk; kt++) {
        *(uint4*)&As[row][wq] = make_uint4(packh2(pa0.x, pa0.y), packh2(pa0.z, pa0.w),
                                           packh2(pa1.x, pa1.y), packh2(pa1.z, pa1.w));
        *(uint4*)&Bs[row][wq] = make_uint4(packh2(pb0.x, pb0.y), packh2(pb0.z, pb0.w),
                                           packh2(pb1.x, pb1.y), packh2(pb1.z, pb1.w));
        __syncthreads();
        if (kt + 1 < nk) {
            const float* Ap2 = Ap + (size_t)(kt + 1) * 16;
            const float* Wp2 = Wp + (size_t)(kt + 1) * 16;
            pa0 = *(const float4*)Ap2; pa1 = *(const float4*)(Ap2 + 4);
            pb0 = *(const float4*)Wp2; pb1 = *(const float4*)(Wp2 + 4);
        }
        unsigned af[4][4], bf[4][2];
#pragma unroll
        for (int mt = 0; mt < 4; mt++) {
            int r0 = wm + mt*16 + grp;
            af[mt][0] = As[r0][qd];
            af[mt][1] = As[r0 + 8][qd];
            af[mt][2] = As[r0][qd + 4];
            af[mt][3] = As[r0 + 8][qd + 4];
        }
#pragma unroll
        for (int nt = 0; nt < 4; nt++) {
            int n0 = wn + nt*8 + grp;
            bf[nt][0] = Bs[n0][qd];
            bf[nt][1] = Bs[n0][qd + 4];
        }
#pragma unroll
        for (int mt = 0; mt < 4; mt++)
#pragma unroll
            for (int nt = 0; nt < 4; nt++)
                mma_f16_k16(c[mt][nt][0], c[mt][nt][1], c[mt][nt][2], c[mt][nt][3],
                            af[mt][0], af[mt][1], af[mt][2], af[mt][3],
                            bf[nt][0], bf[nt][1]);
        __syncthreads();
    }

#pragma unroll
    for (int mt = 0; mt < 4; mt++) {
        int r0 = bm + wm + mt*16 + grp;
#pragma unroll
        for (int nt = 0; nt < 4; nt++) {
            int cb = bn + wn + nt*8 + 2*qd;
            float bi0 = bias[cb], bi1 = bias[cb + 1];
            float v0 = c[mt][nt][0] + bi0;
            float v1 = c[mt][nt][1] + bi1;
            float v2 = c[mt][nt][2] + bi0;
            float v3 = c[mt][nt][3] + bi1;
            if (relu) {
                v0 = fmaxf(v0, 0.f); v1 = fmaxf(v1, 0.f);
                v2 = fmaxf(v2, 0.f); v3 = fmaxf(v3, 0.f);
            }
            if (outHalf) {
                __half* Ch = (__half*)C;
                *(unsigned*)(Ch + (size_t)r0*N + cb)       = packh2(v0, v1);
                *(unsigned*)(Ch + (size_t)(r0 + 8)*N + cb) = packh2(v2, v3);
            } else {
                *(float2*)(C + (size_t)r0*N + cb)       = make_float2(v0, v1);
                *(float2*)(C + (size_t)(r0 + 8)*N + cb) = make_float2(v2, v3);
            }
        }
    }
}

// --------- FP16 flash attention: ex2.f16x2 softmax, mma-computed normalizer ---------
// VT rows 0..31 = V dims, rows 32..39 = 1.0 (ones-rows give l = sum P via 5th n-tile)
#define KST 40
#define VST 456
#define PST 104
#define ATTN_SMEM ((440*KST + 40*VST + 7*16*PST)*2)
__global__ __launch_bounds__(224, 2) void k_attn(const float* __restrict__ abias)
{
    extern __shared__ __half hsm[];
    __half* Ks = hsm;                    // [440][KST]
    __half* VT = hsm + 440*KST;          // [40][VST]
    __half* Ps = VT + 40*VST;            // 7 x [16][PST]
    int b = blockIdx.x >> 3, hh = blockIdx.x & 7;
    int tid = threadIdx.x, lane = tid & 31, warp = tid >> 5;
    int grp = lane >> 2, qd = lane & 3;
    const __half* qkvb = (const __half*)g_qkv + (size_t)b * SSEQ * 768;

    for (int idx = tid; idx < SSEQ*4; idx += 224) {
        int s = idx >> 2, g = idx & 3;
        *(uint4*)(Ks + s*KST + g*8) =
            *(const uint4*)(qkvb + (size_t)s*768 + 256 + hh*32 + g*8);
    }
    for (int idx = tid; idx < SSEQ*16; idx += 224) {
        int s = idx >> 4, w = idx & 15;
        __half2 v = *(const __half2*)(qkvb + (size_t)s*768 + 512 + hh*32 + 2*w);
        VT[(2*w)*VST + s]     = __low2half(v);
        VT[(2*w + 1)*VST + s] = __high2half(v);
    }
    // ones rows 32..39 (for normalizer mma)
    for (int i = tid; i < 8*VST/2; i += 224)
        ((unsigned*)(VT + 32*VST))[i] = 0x3C003C00u;
    __syncthreads();

    __half* Pw = Ps + warp * 16 * PST;
    const float scale = 0.17677669529663687f;   // 1/sqrt(32)
    const float L2E = 1.4426950408889634f;      // log2(e)

    for (int mt = warp; mt < 28; mt += 7) {
        int q0 = mt * 16;
        int qr0 = q0 + grp;      if (qr0 > 439) qr0 = 439;
        int qr1 = q0 + grp + 8;  if (qr1 > 439) qr1 = 439;
        const __half* Qp0 = qkvb + (size_t)qr0*768 + hh*32;
        const __half* Qp1 = qkvb + (size_t)qr1*768 + hh*32;
        unsigned aq[2][4];
#pragma unroll
        for (int ks = 0; ks < 2; ks++) {
            aq[ks][0] = *(const unsigned*)(Qp0 + ks*16 + 2*qd);
            aq[ks][1] = *(const unsigned*)(Qp1 + ks*16 + 2*qd);
            aq[ks][2] = *(const unsigned*)(Qp0 + ks*16 + 2*qd + 8);
            aq[ks][3] = *(const unsigned*)(Qp1 + ks*16 + 2*qd + 8);
        }
        const float* bp0 = abias + (size_t)qr0 * SSEQ;
        const float* bp1 = abias + (size_t)qr1 * SSEQ;

        float o[5][4];   // o[4] = normalizer accumulator (all columns = sum P)
#pragma unroll
        for (int dc = 0; dc < 5; dc++)
#pragma unroll
            for (int r = 0; r < 4; r++) o[dc][r] = 0.f;

        for (int ch = 0; ch < 5; ch++) {
            int kbase = ch * 88;
#pragma unroll
            for (int nc = 0; nc < 11; nc++) {
                int n0 = kbase + nc*8;
                float c0 = 0.f, c1 = 0.f, c2 = 0.f, c3 = 0.f;
                const __half* kr = Ks + (n0 + grp)*KST;
#pragma unroll
                for (int ks = 0; ks < 2; ks++) {
                    unsigned b0 = *(const unsigned*)(kr + ks*16 + 2*qd);
                    unsigned b1 = *(const unsigned*)(kr + ks*16 + 2*qd + 8);
                    mma_f16_k16(c0, c1, c2, c3,
                                aq[ks][0], aq[ks][1], aq[ks][2], aq[ks][3], b0, b1);
                }
                float2 bb0 = *(const float2*)(bp0 + n0 + 2*qd);
                float2 bb1 = *(const float2*)(bp1 + n0 + 2*qd);
                // s*log2e, packed, then one f16x2 ex2 per pair
                float t0 = fmaf(c0, scale, bb0.x) * L2E;
                float t1 = fmaf(c1, scale, bb0.y) * L2E;
                float t2 = fmaf(c2, scale, bb1.x) * L2E;
                float t3 = fmaf(c3, scale, bb1.y) * L2E;
                *(unsigned*)(Pw + grp*PST + nc*8 + 2*qd)       = ex2h2(packh2(t0, t1));
                *(unsigned*)(Pw + (grp + 8)*PST + nc*8 + 2*qd) = ex2h2(packh2(t2, t3));
            }
            __syncwarp();
#pragma unroll
            for (int ks = 0; ks < 5; ks++) {
                unsigned ap0 = *(const unsigned*)(Pw + grp*PST + ks*16 + 2*qd);
                unsigned ap1 = *(const unsigned*)(Pw + (grp + 8)*PST + ks*16 + 2*qd);
                unsigned ap2 = *(const unsigned*)(Pw + grp*PST + ks*16 + 2*qd + 8);
                unsigned ap3 = *(const unsigned*)(Pw + (grp + 8)*PST + ks*16 + 2*qd + 8);
#pragma unroll
                for (int dc = 0; dc < 5; dc++) {
                    const __half* vr = VT + (dc*8 + grp)*VST + kbase + ks*16;
                    unsigned b0 = *(const unsigned*)(vr + 2*qd);
                    unsigned b1 = *(const unsigned*)(vr + 2*qd + 8);
                    mma_f16_k16(o[dc][0], o[dc][1], o[dc][2], o[dc][3],
                                ap0, ap1, ap2, ap3, b0, b1);
                }
            }
            {
                unsigned ap0 = *(const unsigned*)(Pw + grp*PST + 80 + 2*qd);
                unsigned ap1 = *(const unsigned*)(Pw + (grp + 8)*PST + 80 + 2*qd);
#pragma unroll
                for (int dc = 0; dc < 5; dc++) {
                    const __half* vr = VT + (dc*8 + grp)*VST + kbase + 80;
                    unsigned b0 = *(const unsigned*)(vr + 2*qd);
                    mma_f16_k8(o[dc][0], o[dc][1], o[dc][2], o[dc][3], ap0, ap1, b0);
                }
            }
            __syncwarp();
        }
        // normalizer straight from the ones-tile C fragment (no shfl)
        float inv0 = 1.f / o[4][0], inv1 = 1.f / o[4][2];
        int qa = q0 + grp, qb = q0 + grp + 8;
#pragma unroll
        for (int dc = 0; dc < 4; dc++) {
            int dcol = hh*32 + dc*8 + 2*qd;
            if (qa < SSEQ)
                *(float2*)(g_t1 + ((size_t)b*SSEQ + qa)*DDIM + dcol) =
                    make_float2(o[dc][0]*inv0, o[dc][1]*inv0);
            if (qb < SSEQ)
                *(float2*)(g_t1 + ((size_t)b*SSEQ + qb)*DDIM + dcol) =
                    make_float2(o[dc][2]*inv1, o[dc][3]*inv1);
        }
    }
}

// ------------- fused residual + layernorm, vectorized: one warp per row -------------
__global__ __launch_bounds__(256) void k_ln(const float* __restrict__ add,
                                            const float* __restrict__ gam,
                                            const float* __restrict__ bet)
{
    int row = blockIdx.x * 8 + (threadIdx.x >> 5);
    int lane = threadIdx.x & 31;
    size_t base = (size_t)row * DDIM + lane * 8;
    float4 h0 = *(const float4*)(g_h + base);
    float4 h1 = *(const float4*)(g_h + base + 4);
    float4 a0 = *(const float4*)(add + base);
    float4 a1 = *(const float4*)(add + base + 4);
    float v[8];
    v[0] = h0.x + a0.x; v[1] = h0.y + a0.y; v[2] = h0.z + a0.z; v[3] = h0.w + a0.w;
    v[4] = h1.x + a1.x; v[5] = h1.y + a1.y; v[6] = h1.z + a1.z; v[7] = h1.w + a1.w;
    float s1 = 0.f, s2 = 0.f;
#pragma unroll
    for (int j = 0; j < 8; j++) { s1 += v[j]; s2 += v[j]*v[j]; }
#pragma unroll
    for (int o = 16; o > 0; o >>= 1) {
        s1 += __shfl_xor_sync(~0u, s1, o);
        s2 += __shfl_xor_sync(~0u, s2, o);
    }
    float m = s1 * (1.f/256.f);
    float var = s2 * (1.f/256.f) - m*m;
    float inv = rsqrtf(var + 1e-5f);
    float4 g0 = *(const float4*)(gam + lane*8);
    float4 g1 = *(const float4*)(gam + lane*8 + 4);
    float4 b0 = *(const float4*)(bet + lane*8);
    float4 b1 = *(const float4*)(bet + lane*8 + 4);
    float4 o0, o1;
    o0.x = (v[0]-m)*inv*g0.x + b0.x; o0.y = (v[1]-m)*inv*g0.y + b0.y;
    o0.z = (v[2]-m)*inv*g0.z + b0.z; o0.w = (v[3]-m)*inv*g0.w + b0.w;
    o1.x = (v[4]-m)*inv*g1.x + b1.x; o1.y = (v[5]-m)*inv*g1.y + b1.y;
    o1.z = (v[6]-m)*inv*g1.z + b1.z; o1.w = (v[7]-m)*inv*g1.w + b1.w;
    *(float4*)(g_h + base)     = o0;
    *(float4*)(g_h + base + 4) = o1;
}

// --------- FP16 mma conv (verified) ---------
#define CVSTH 792
#define WSTH  18
#define CONV_SMEM ((16*CVSTH + 9*32*WSTH)*4)
__global__ __launch_bounds__(256, 2) void k_conv(
    const float* __restrict__ cw1, const float* __restrict__ cb1,
    const float* __restrict__ cw2, const float* __restrict__ cb2,
    const float* __restrict__ cw3, const float* __restrict__ cb3,
    float* __restrict__ out)
{
    extern __shared__ unsigned usm[];
    unsigned* cx  = usm;                  // [16][CVSTH]
    unsigned* swt = usm + 16*CVSTH;       // [9][32][WSTH]
    int b = blockIdx.x >> 3, gch = blockIdx.x & 7;
    int tid = threadIdx.x, lane = tid & 31, warp = tid >> 5;
    int grp = lane >> 2, qd = lane & 3;
    const float* hb = g_h + (size_t)b * SSEQ * DDIM;

    for (int i = tid; i < 16*CVSTH; i += 256) cx[i] = 0u;
    __syncthreads();
    for (int idx = tid; idx < SSEQ*16; idx += 256) {
        int p = idx >> 4, w = idx & 15;
        int cidx = p + 6*(p/22) + 87;
        float2 v = *(const float2*)(hb + (size_t)p*DDIM + gch*32 + 2*w);
        cx[w*CVSTH + cidx] = packh2(v.x, v.y);
    }

    const float* cws[3] = {cw1, cw2, cw3};
    const float* cbs[3] = {cb1, cb2, cb3};

    int mt0 = warp;
#pragma unroll
    for (int half = 0; half < 2; half++) {
        int tA = mt0 + 16*half;
        int pxA0 = tA*16 + grp;
        int pxA1 = pxA0 + 8;
        int pxB0 = (tA + 8)*16 + grp;
        int pxB1 = pxB0 + 8;
        int ciA0 = pxA0 + 6*(pxA0/22) + 87;
        int ciA1 = pxA1 + 6*(pxA1/22) + 87;
        int ciB0 = pxB0 + 6*(pxB0/22) + 87;
        int ciB1 = pxB1 + 6*(pxB1/22) + 87;

        float tot[2][4][4];
#pragma unroll
        for (int p = 0; p < 2; p++)
#pragma unroll
            for (int nt = 0; nt < 4; nt++)
#pragma unroll
                for (int r = 0; r < 4; r++) tot[p][nt][r] = 0.f;

        for (int cv = 0; cv < 3; cv++) {
            int dil = cv + 1;
            __syncthreads();
            const float* src = cws[cv] + (size_t)gch * 32 * 288;
            for (int i = tid; i < 32*9*16; i += 256) {
                int oc = i / 144, rem = i - oc*144;
                int t = rem / 16, w = rem - t*16;
                float w0 = src[oc*288 + (2*w)*9 + t];
                float w1 = src[oc*288 + (2*w + 1)*9 + t];
                swt[t*32*WSTH + oc*WSTH + w] = packh2(w0, w1);
            }
            __syncthreads();

            float acc[2][4][4];
#pragma unroll
            for (int p = 0; p < 2; p++)
#pragma unroll
                for (int nt = 0; nt < 4; nt++)
#pragma unroll
                    for (int r = 0; r < 4; r++) acc[p][nt][r] = 0.f;

            for (int t = 0; t < 9; t++) {
                int sh = (t/3 - 1)*dil*28 + (t%3 - 1)*dil;
                const unsigned* wt = swt + t*32*WSTH;
#pragma unroll
                for (int ks = 0; ks < 2; ks++) {
                    const unsigned* r0 = cx + (ks*8 + qd)*CVSTH + sh;
                    const unsigned* r1 = cx + (ks*8 + qd + 4)*CVSTH + sh;
                    unsigned aA0 = r0[ciA0], aA1 = r0[ciA1];
                    unsigned aA2 = r1[ciA0], aA3 = r1[ciA1];
                    unsigned aB0 = r0[ciB0], aB1 = r0[ciB1];
                    unsigned aB2 = r1[ciB0], aB3 = r1[ciB1];
#pragma unroll
                    for (int nt = 0; nt < 4; nt++) {
                        unsigned b0 = wt[(nt*8 + grp)*WSTH + ks*8 + qd];
                        unsigned b1 = wt[(nt*8 + grp)*WSTH + ks*8 + qd + 4];
                        mma_f16_k16(acc[0][nt][0], acc[0][nt][1], acc[0][nt][2], acc[0][nt][3],
                                    aA0, aA1, aA2, aA3, b0, b1);
                        mma_f16_k16(acc[1][nt][0], acc[1][nt][1], acc[1][nt][2], acc[1][nt][3],
                                    aB0, aB1, aB2, aB3, b0, b1);
                    }
                }
            }
#pragma unroll
            for (int nt = 0; nt < 4; nt++) {
                float bi0 = cbs[cv][gch*32 + nt*8 + 2*qd];
                float bi1 = cbs[cv][gch*32 + nt*8 + 2*qd + 1];
#pragma unroll
                for (int p = 0; p < 2; p++) {
                    tot[p][nt][0] += fmaxf(acc[p][nt][0] + bi0, 0.f);
                    tot[p][nt][1] += fmaxf(acc[p][nt][1] + bi1, 0.f);
                    tot[p][nt][2] += fmaxf(acc[p][nt][2] + bi0, 0.f);
                    tot[p][nt][3] += fmaxf(acc[p][nt][3] + bi1, 0.f);
                }
            }
        }

        float* ob = out + (size_t)b * SSEQ * DDIM;
#pragma unroll
        for (int p = 0; p < 2; p++) {
            int px0 = (tA + 8*p)*16 + grp;
            int px1 = px0 + 8;
#pragma unroll
            for (int nt = 0; nt < 4; nt++) {
                int ch = gch*32 + nt*8 + 2*qd;
                if (px0 < SSEQ) {
                    float r0 = hb[(size_t)px0*DDIM + ch];
                    float r1 = hb[(size_t)px0*DDIM + ch + 1];
                    *(float2*)(ob + (size_t)px0*DDIM + ch) =
                        make_float2(0.5f*(r0 + tot[p][nt][0]), 0.5f*(r1 + tot[p][nt][1]));
                }
                if (px1 < SSEQ) {
                    float r2 = hb[(size_t)px1*DDIM + ch];
                    float r3 = hb[(size_t)px1*DDIM + ch + 1];
                    *(float2*)(ob + (size_t)px1*DDIM + ch) =
                        make_float2(0.5f*(r2 + tot[p][nt][2]), 0.5f*(r3 + tot[p][nt][3]));
                }
            }
        }
        __syncthreads();
    }
}

// ------------------------------ launcher ------------------------------
extern "C" void kernel_launch(void* const* d_in, const int* in_sizes, int n_in,
                              void* d_out, int out_size)
{
    const int* x    = (const int*)d_in[0];
    const float* ev   = (const float*)d_in[2];
    const float* px   = (const float*)d_in[3];
    const float* py   = (const float*)d_in[4];
    const float* st   = (const float*)d_in[5];
    const int* tkx = (const int*)d_in[6];
    const int* tky = (const int*)d_in[7];
    const int* tks = (const int*)d_in[8];
    const float* abias = (const float*)d_in[9];
    const float* Wqkv = (const float*)d_in[10];
    const float* bqkv = (const float*)d_in[11];
    const float* Wo   = (const float*)d_in[12];
    const float* bo   = (const float*)d_in[13];
    const float* W1   = (const float*)d_in[14];
    const float* b1   = (const float*)d_in[15];
    const float* W2   = (const float*)d_in[16];
    const float* b2   = (const float*)d_in[17];
    const float* ln1s = (const float*)d_in[18];
    const float* ln1b = (const float*)d_in[19];
    const float* ln2s = (const float*)d_in[20];
    const float* ln2b = (const float*)d_in[21];
    const float* cw1  = (const float*)d_in[22];
    const float* cb1  = (const float*)d_in[23];
    const float* cw2  = (const float*)d_in[24];
    const float* cb2  = (const float*)d_in[25];
    const float* cw3  = (const float*)d_in[26];
    const float* cb3  = (const float*)d_in[27];
    float* out = (float*)d_out;

    float *hP, *qkvP, *t1P, *t2P;
    cudaGetSymbolAddress((void**)&hP,   g_h);
    cudaGetSymbolAddress((void**)&qkvP, g_qkv);
    cudaGetSymbolAddress((void**)&t1P,  g_t1);
    cudaGetSymbolAddress((void**)&t2P,  g_t2);

    cudaFuncSetAttribute(k_attn, cudaFuncAttributeMaxDynamicSharedMemorySize, ATTN_SMEM);
    cudaFuncSetAttribute(k_conv, cudaFuncAttributeMaxDynamicSharedMemorySize, CONV_SMEM);

    k_embed<<<BS_, 256>>>(x, ev, px, py, st, tkx, tky, tks);

    for (int l = 0; l < LNUM; l++) {
        k_gemm<<<dim3(6, 220), 256>>>(hP, Wqkv + (size_t)l*768*256, bqkv + l*768,
                                      qkvP, BS_, 768, 256, 0, 1);
        k_attn<<<BB*HN, 224, ATTN_SMEM>>>(abias);
        k_gemm<<<dim3(2, 220), 256>>>(t1P, Wo + (size_t)l*256*256, bo + l*256,
                                      t2P, BS_, 256, 256, 0, 0);
        k_ln<<<BS_/8, 256>>>(t2P, ln1s + l*256, ln1b + l*256);
        k_gemm<<<dim3(4, 220), 256>>>(hP, W1 + (size_t)l*512*256, b1 + l*512,
                                      t1P, BS_, 512, 256, 1, 0);
        k_gemm<<<dim3(2, 220), 256>>>(t1P, W2 + (size_t)l*256*512, b2 + l*256,
                                      t2P, BS_, 256, 512, 0, 0);
        k_ln<<<BS_/8, 256>>>(t2P, ln2s + l*256, ln2b + l*256);
        float* cout = (l == LNUM-1) ? out : hP;
        k_conv<<<BB*HN, 256, CONV_SMEM>>>(cw1 + (size_t)l*256*288, cb1 + l*256,
                                          cw2 + (size_t)l*256*288, cb2 + l*256,
                                          cw3 + (size_t)l*256*288, cb3 + l*256,
                                          cout);
    }
}

// round 15
// speedup vs baseline: 1.2214x; 1.2214x over previous
#include <cuda_runtime.h>
#include <cuda_bf16.h>
#include <cuda_fp16.h>

#define BB 64
#define SSEQ 440
#define DDIM 256
#define HN 8
#define FFD 512
#define LNUM 6
#define BS_ (BB*SSEQ)   // 28160

// ------------ static device scratch (no allocation) ------------
__device__ float  g_h[(size_t)BS_*DDIM];
__device__ __half g_hh[(size_t)BS_*DDIM];          // fp16 mirror of g_h
__device__ __half g_qkv[(size_t)BS_*3*DDIM];
__device__ __half g_t1[(size_t)BS_*FFD];           // attn out / ff1 out (fp16)
__device__ float  g_t2[(size_t)BS_*DDIM];
// converted weights: wqkv | wo | w1 | w2
#define WH_QKV 0
#define WH_O   (6*768*256)
#define WH_1   (WH_O + 6*256*256)
#define WH_2   (WH_1 + 6*512*256)
#define WH_TOT (WH_2 + 6*256*512)
__device__ __half g_wh[WH_TOT];

__device__ __forceinline__ void mma_f16_k16(float& c0, float& c1, float& c2, float& c3,
                                            unsigned a0, unsigned a1, unsigned a2, unsigned a3,
                                            unsigned b0, unsigned b1)
{
    asm volatile(
        "mma.sync.aligned.m16n8k16.row.col.f32.f16.f16.f32 "
        "{%0,%1,%2,%3}, {%4,%5,%6,%7}, {%8,%9}, {%0,%1,%2,%3};"
        : "+f"(c0), "+f"(c1), "+f"(c2), "+f"(c3)
        : "r"(a0), "r"(a1), "r"(a2), "r"(a3), "r"(b0), "r"(b1));
}

__device__ __forceinline__ void mma_f16_k8(float& c0, float& c1, float& c2, float& c3,
                                           unsigned a0, unsigned a1, unsigned b0)
{
    asm volatile(
        "mma.sync.aligned.m16n8k8.row.col.f32.f16.f16.f32 "
        "{%0,%1,%2,%3}, {%4,%5}, {%6}, {%0,%1,%2,%3};"
        : "+f"(c0), "+f"(c1), "+f"(c2), "+f"(c3)
        : "r"(a0), "r"(a1), "r"(b0));
}

__device__ __forceinline__ unsigned packh2(float a, float b) {
    __half2 h = __floats2half2_rn(a, b);
    return *(unsigned*)&h;
}

__device__ __forceinline__ void cpa16(unsigned saddr, const void* g) {
    asm volatile("cp.async.ca.shared.global [%0], [%1], 16;" :: "r"(saddr), "l"(g));
}

// ------------------------ weight fp32->fp16 convert ------------------------
__global__ void k_cvt(const float* __restrict__ in, __half* __restrict__ dst, int n)
{
    int i = blockIdx.x * 256 + threadIdx.x;
    if (i < n) dst[i] = __float2half_rn(in[i]);
}

// ------------------------ embedding ------------------------
__global__ void k_embed(const int* __restrict__ x,
                        const float* __restrict__ ev, const float* __restrict__ px,
                        const float* __restrict__ py, const float* __restrict__ st,
                        const int* __restrict__ tkx, const int* __restrict__ tky,
                        const int* __restrict__ tks)
{
    int bs = blockIdx.x;
    int s = bs % SSEQ;
    int d = threadIdx.x;
    int xi = x[bs];
    float v = ev[xi*DDIM + d] + px[tkx[s]*DDIM + d] + py[tky[s]*DDIM + d] + st[tks[s]*DDIM + d];
    g_h[(size_t)bs*DDIM + d] = v;
    g_hh[(size_t)bs*DDIM + d] = __float2half_rn(v);
}

// ---- FP16-input cp.async 3-stage pipelined GEMM ----
// A[M,K] half, W[N,K] half, k-step 32, smem rows stride 40 halves (20 words)
#define GST 40
#define GEMM_SMEM (2 * 3 * 128 * GST * 2)   // A + B, 3 stages each
__global__ __launch_bounds__(256, 2) void k_gemm_h(
    const __half* __restrict__ A, const __half* __restrict__ W,
    const float* __restrict__ bias, float* __restrict__ C,
    int M, int N, int K, int relu, int outHalf)
{
    extern __shared__ __half gsm[];
    __half* As = gsm;                 // [3][128][GST]
    __half* Bs = gsm + 3*128*GST;
    int tid = threadIdx.x;
    int bm = blockIdx.y * 128, bn = blockIdx.x * 128;
    int row = tid >> 1, ko = (tid & 1) * 16;

    const __half* Asrc = A + (size_t)(bm + row) * K + ko;
    const __half* Bsrc = W + (size_t)(bn + row) * K + ko;
    unsigned aBase = (unsigned)__cvta_generic_to_shared(As + row*GST + ko);
    unsigned bBase = (unsigned)__cvta_generic_to_shared(Bs + row*GST + ko);

    int nk = K >> 5;
    // prologue: stages 0,1
#pragma unroll
    for (int s = 0; s < 2; s++) {
        unsigned ad = aBase + (s)*128*GST*2;
        unsigned bd = bBase + (s)*128*GST*2;
        cpa16(ad, Asrc + s*32); cpa16(ad + 16, Asrc + s*32 + 8);
        cpa16(bd, Bsrc + s*32); cpa16(bd + 16, Bsrc + s*32 + 8);
        asm volatile("cp.async.commit_group;");
    }

    int lane = tid & 31, warp = tid >> 5;
    int wm = (warp & 1) * 64, wn = (warp >> 1) * 32;
    int grp = lane >> 2, qd = lane & 3;

    float c[4][4][4];
#pragma unroll
    for (int mt = 0; mt < 4; mt++)
#pragma unroll
        for (int nt = 0; nt < 4; nt++)
#pragma unroll
            for (int r = 0; r < 4; r++) c[mt][nt][r] = 0.f;

    for (int kt = 0; kt < nk; kt++) {
        asm volatile("cp.async.wait_group 1;");
        __syncthreads();
        const unsigned* Aw = (const unsigned*)(As + (kt % 3)*128*GST);
        const unsigned* Bw = (const unsigned*)(Bs + (kt % 3)*128*GST);
#pragma unroll
        for (int kh = 0; kh < 2; kh++) {
            unsigned af[4][4], bf[4][2];
#pragma unroll
            for (int mt = 0; mt < 4; mt++) {
                int r0 = wm + mt*16 + grp;
                af[mt][0] = Aw[r0*20 + kh*8 + qd];
                af[mt][1] = Aw[(r0 + 8)*20 + kh*8 + qd];
                af[mt][2] = Aw[r0*20 + kh*8 + qd + 4];
                af[mt][3] = Aw[(r0 + 8)*20 + kh*8 + qd + 4];
            }
#pragma unroll
            for (int nt = 0; nt < 4; nt++) {
                int n0 = wn + nt*8 + grp;
                bf[nt][0] = Bw[n0*20 + kh*8 + qd];
                bf[nt][1] = Bw[n0*20 + kh*8 + qd + 4];
            }
#pragma unroll
            for (int mt = 0; mt < 4; mt++)
#pragma unroll
                for (int nt = 0; nt < 4; nt++)
                    mma_f16_k16(c[mt][nt][0], c[mt][nt][1], c[mt][nt][2], c[mt][nt][3],
                                af[mt][0], af[mt][1], af[mt][2], af[mt][3],
                                bf[nt][0], bf[nt][1]);
        }
        int s = kt + 2;
        if (s < nk) {
            unsigned ad = aBase + (s % 3)*128*GST*2;
            unsigned bd = bBase + (s % 3)*128*GST*2;
            cpa16(ad, Asrc + s*32); cpa16(ad + 16, Asrc + s*32 + 8);
            cpa16(bd, Bsrc + s*32); cpa16(bd + 16, Bsrc + s*32 + 8);
        }
        asm volatile("cp.async.commit_group;");
    }

#pragma unroll
    for (int mt = 0; mt < 4; mt++) {
        int r0 = bm + wm + mt*16 + grp;
#pragma unroll
        for (int nt = 0; nt < 4; nt++) {
            int cb = bn + wn + nt*8 + 2*qd;
            float bi0 = bias[cb], bi1 = bias[cb + 1];
            float v0 = c[mt][nt][0] + bi0;
            float v1 = c[mt][nt][1] + bi1;
            float v2 = c[mt][nt][2] + bi0;
            float v3 = c[mt][nt][3] + bi1;
            if (relu) {
                v0 = fmaxf(v0, 0.f); v1 = fmaxf(v1, 0.f);
                v2 = fmaxf(v2, 0.f); v3 = fmaxf(v3, 0.f);
            }
            if (outHalf) {
                __half* Ch = (__half*)C;
                *(unsigned*)(Ch + (size_t)r0*N + cb)       = packh2(v0, v1);
                *(unsigned*)(Ch + (size_t)(r0 + 8)*N + cb) = packh2(v2, v3);
            } else {
                *(float2*)(C + (size_t)r0*N + cb)       = make_float2(v0, v1);
                *(float2*)(C + (size_t)(r0 + 8)*N + cb) = make_float2(v2, v3);
            }
        }
    }
}

// --------- FP16 flash attention (R13 structure, fp16 output) ---------
#define KST 40
#define VST 456
#define PST 104
#define ATTN_SMEM ((440*KST + 32*VST + 7*16*PST)*2)
__global__ __launch_bounds__(224, 2) void k_attn(const float* __restrict__ abias)
{
    extern __shared__ __half hsm[];
    __half* Ks = hsm;                    // [440][KST]
    __half* VT = hsm + 440*KST;          // [32][VST]
    __half* Ps = VT + 32*VST;            // 7 x [16][PST]
    int b = blockIdx.x >> 3, hh = blockIdx.x & 7;
    int tid = threadIdx.x, lane = tid & 31, warp = tid >> 5;
    int grp = lane >> 2, qd = lane & 3;
    const __half* qkvb = g_qkv + (size_t)b * SSEQ * 768;

    for (int idx = tid; idx < SSEQ*4; idx += 224) {
        int s = idx >> 2, g = idx & 3;
        *(uint4*)(Ks + s*KST + g*8) =
            *(const uint4*)(qkvb + (size_t)s*768 + 256 + hh*32 + g*8);
    }
    for (int idx = tid; idx < SSEQ*16; idx += 224) {
        int s = idx >> 4, w = idx & 15;
        __half2 v = *(const __half2*)(qkvb + (size_t)s*768 + 512 + hh*32 + 2*w);
        VT[(2*w)*VST + s]     = __low2half(v);
        VT[(2*w + 1)*VST + s] = __high2half(v);
    }
    __syncthreads();

    __half* Pw = Ps + warp * 16 * PST;
    const float scale = 0.17677669529663687f;

    for (int mt = warp; mt < 28; mt += 7) {
        int q0 = mt * 16;
        int qr0 = q0 + grp;      if (qr0 > 439) qr0 = 439;
        int qr1 = q0 + grp + 8;  if (qr1 > 439) qr1 = 439;
        const __half* Qp0 = qkvb + (size_t)qr0*768 + hh*32;
        const __half* Qp1 = qkvb + (size_t)qr1*768 + hh*32;
        unsigned aq[2][4];
#pragma unroll
        for (int ks = 0; ks < 2; ks++) {
            aq[ks][0] = *(const unsigned*)(Qp0 + ks*16 + 2*qd);
            aq[ks][1] = *(const unsigned*)(Qp1 + ks*16 + 2*qd);
            aq[ks][2] = *(const unsigned*)(Qp0 + ks*16 + 2*qd + 8);
            aq[ks][3] = *(const unsigned*)(Qp1 + ks*16 + 2*qd + 8);
        }
        const float* bp0 = abias + (size_t)qr0 * SSEQ;
        const float* bp1 = abias + (size_t)qr1 * SSEQ;

        float o[4][4];
#pragma unroll
        for (int dc = 0; dc < 4; dc++)
#pragma unroll
            for (int r = 0; r < 4; r++) o[dc][r] = 0.f;
        float l0 = 0.f, l1 = 0.f;

        for (int ch = 0; ch < 5; ch++) {
            int kbase = ch * 88;
            float cs[11][4];
#pragma unroll
            for (int nc = 0; nc < 11; nc++) {
                int n0 = kbase + nc*8;
                float c0 = 0.f, c1 = 0.f, c2 = 0.f, c3 = 0.f;
                const __half* kr = Ks + (n0 + grp)*KST;
#pragma unroll
                for (int ks = 0; ks < 2; ks++) {
                    unsigned b0 = *(const unsigned*)(kr + ks*16 + 2*qd);
                    unsigned b1 = *(const unsigned*)(kr + ks*16 + 2*qd + 8);
                    mma_f16_k16(c0, c1, c2, c3,
                                aq[ks][0], aq[ks][1], aq[ks][2], aq[ks][3], b0, b1);
                }
                float2 bb0 = *(const float2*)(bp0 + n0 + 2*qd);
                float2 bb1 = *(const float2*)(bp1 + n0 + 2*qd);
                cs[nc][0] = fmaf(c0, scale, bb0.x);
                cs[nc][1] = fmaf(c1, scale, bb0.y);
                cs[nc][2] = fmaf(c2, scale, bb1.x);
                cs[nc][3] = fmaf(c3, scale, bb1.y);
            }
#pragma unroll
            for (int nc = 0; nc < 11; nc++) {
                float e0 = __expf(cs[nc][0]);
                float e1 = __expf(cs[nc][1]);
                float e2 = __expf(cs[nc][2]);
                float e3 = __expf(cs[nc][3]);
                l0 += e0 + e1; l1 += e2 + e3;
                *(unsigned*)(Pw + grp*PST + nc*8 + 2*qd)       = packh2(e0, e1);
                *(unsigned*)(Pw + (grp + 8)*PST + nc*8 + 2*qd) = packh2(e2, e3);
            }
            __syncwarp();
#pragma unroll
            for (int ks = 0; ks < 5; ks++) {
                unsigned ap0 = *(const unsigned*)(Pw + grp*PST + ks*16 + 2*qd);
                unsigned ap1 = *(const unsigned*)(Pw + (grp + 8)*PST + ks*16 + 2*qd);
                unsigned ap2 = *(const unsigned*)(Pw + grp*PST + ks*16 + 2*qd + 8);
                unsigned ap3 = *(const unsigned*)(Pw + (grp + 8)*PST + ks*16 + 2*qd + 8);
#pragma unroll
                for (int dc = 0; dc < 4; dc++) {
                    const __half* vr = VT + (dc*8 + grp)*VST + kbase + ks*16;
                    unsigned b0 = *(const unsigned*)(vr + 2*qd);
                    unsigned b1 = *(const unsigned*)(vr + 2*qd + 8);
                    mma_f16_k16(o[dc][0], o[dc][1], o[dc][2], o[dc][3],
                                ap0, ap1, ap2, ap3, b0, b1);
                }
            }
            {
                unsigned ap0 = *(const unsigned*)(Pw + grp*PST + 80 + 2*qd);
                unsigned ap1 = *(const unsigned*)(Pw + (grp + 8)*PST + 80 + 2*qd);
#pragma unroll
                for (int dc = 0; dc < 4; dc++) {
                    const __half* vr = VT + (dc*8 + grp)*VST + kbase + 80;
                    unsigned b0 = *(const unsigned*)(vr + 2*qd);
                    mma_f16_k8(o[dc][0], o[dc][1], o[dc][2], o[dc][3], ap0, ap1, b0);
                }
            }
            __syncwarp();
        }
        l0 += __shfl_xor_sync(~0u, l0, 1);
        l0 += __shfl_xor_sync(~0u, l0, 2);
        l1 += __shfl_xor_sync(~0u, l1, 1);
        l1 += __shfl_xor_sync(~0u, l1, 2);
        float inv0 = 1.f / l0, inv1 = 1.f / l1;
        int qa = q0 + grp, qb = q0 + grp + 8;
#pragma unroll
        for (int dc = 0; dc < 4; dc++) {
            int dcol = hh*32 + dc*8 + 2*qd;
            if (qa < SSEQ)
                *(unsigned*)(g_t1 + ((size_t)b*SSEQ + qa)*DDIM + dcol) =
                    packh2(o[dc][0]*inv0, o[dc][1]*inv0);
            if (qb < SSEQ)
                *(unsigned*)(g_t1 + ((size_t)b*SSEQ + qb)*DDIM + dcol) =
                    packh2(o[dc][2]*inv1, o[dc][3]*inv1);
        }
    }
}

// ------------- fused residual + layernorm; writes f32 + f16 mirror -------------
__global__ __launch_bounds__(256) void k_ln(const float* __restrict__ add,
                                            const float* __restrict__ gam,
                                            const float* __restrict__ bet)
{
    int row = blockIdx.x * 8 + (threadIdx.x >> 5);
    int lane = threadIdx.x & 31;
    size_t base = (size_t)row * DDIM + lane * 8;
    float4 h0 = *(const float4*)(g_h + base);
    float4 h1 = *(const float4*)(g_h + base + 4);
    float4 a0 = *(const float4*)(add + base);
    float4 a1 = *(const float4*)(add + base + 4);
    float v[8];
    v[0] = h0.x + a0.x; v[1] = h0.y + a0.y; v[2] = h0.z + a0.z; v[3] = h0.w + a0.w;
    v[4] = h1.x + a1.x; v[5] = h1.y + a1.y; v[6] = h1.z + a1.z; v[7] = h1.w + a1.w;
    float s1 = 0.f, s2 = 0.f;
#pragma unroll
    for (int j = 0; j < 8; j++) { s1 += v[j]; s2 += v[j]*v[j]; }
#pragma unroll
    for (int o = 16; o > 0; o >>= 1) {
        s1 += __shfl_xor_sync(~0u, s1, o);
        s2 += __shfl_xor_sync(~0u, s2, o);
    }
    float m = s1 * (1.f/256.f);
    float var = s2 * (1.f/256.f) - m*m;
    float inv = rsqrtf(var + 1e-5f);
    float4 g0 = *(const float4*)(gam + lane*8);
    float4 g1 = *(const float4*)(gam + lane*8 + 4);
    float4 b0 = *(const float4*)(bet + lane*8);
    float4 b1 = *(const float4*)(bet + lane*8 + 4);
    float r[8];
    r[0] = (v[0]-m)*inv*g0.x + b0.x; r[1] = (v[1]-m)*inv*g0.y + b0.y;
    r[2] = (v[2]-m)*inv*g0.z + b0.z; r[3] = (v[3]-m)*inv*g0.w + b0.w;
    r[4] = (v[4]-m)*inv*g1.x + b1.x; r[5] = (v[5]-m)*inv*g1.y + b1.y;
    r[6] = (v[6]-m)*inv*g1.z + b1.z; r[7] = (v[7]-m)*inv*g1.w + b1.w;
    *(float4*)(g_h + base)     = make_float4(r[0], r[1], r[2], r[3]);
    *(float4*)(g_h + base + 4) = make_float4(r[4], r[5], r[6], r[7]);
    uint2 p0 = make_uint2(packh2(r[0], r[1]), packh2(r[2], r[3]));
    uint2 p1 = make_uint2(packh2(r[4], r[5]), packh2(r[6], r[7]));
    *(uint2*)(g_hh + base)     = p0;
    *(uint2*)(g_hh + base + 4) = p1;
}

// --------- FP16 mma conv; canvas from g_hh, residual from g_h; writes f32 + mirror ---------
#define CVSTH 792
#define WSTH  18
#define CONV_SMEM ((16*CVSTH + 9*32*WSTH)*4)
__global__ __launch_bounds__(256, 2) void k_conv(
    const float* __restrict__ cw1, const float* __restrict__ cb1,
    const float* __restrict__ cw2, const float* __restrict__ cb2,
    const float* __restrict__ cw3, const float* __restrict__ cb3,
    float* __restrict__ out)
{
    extern __shared__ unsigned usm[];
    unsigned* cx  = usm;                  // [16][CVSTH]
    unsigned* swt = usm + 16*CVSTH;       // [9][32][WSTH]
    int b = blockIdx.x >> 3, gch = blockIdx.x & 7;
    int tid = threadIdx.x, lane = tid & 31, warp = tid >> 5;
    int grp = lane >> 2, qd = lane & 3;
    const float*  hb  = g_h  + (size_t)b * SSEQ * DDIM;
    const __half* hbh = g_hh + (size_t)b * SSEQ * DDIM;

    for (int i = tid; i < 16*CVSTH; i += 256) cx[i] = 0u;
    __syncthreads();
    for (int idx = tid; idx < SSEQ*16; idx += 256) {
        int p = idx >> 4, w = idx & 15;
        int cidx = p + 6*(p/22) + 87;
        cx[w*CVSTH + cidx] = *(const unsigned*)(hbh + (size_t)p*DDIM + gch*32 + 2*w);
    }

    const float* cws[3] = {cw1, cw2, cw3};
    const float* cbs[3] = {cb1, cb2, cb3};

    int mt0 = warp;
#pragma unroll
    for (int half = 0; half < 2; half++) {
        int tA = mt0 + 16*half;
        int pxA0 = tA*16 + grp;
        int pxA1 = pxA0 + 8;
        int pxB0 = (tA + 8)*16 + grp;
        int pxB1 = pxB0 + 8;
        int ciA0 = pxA0 + 6*(pxA0/22) + 87;
        int ciA1 = pxA1 + 6*(pxA1/22) + 87;
        int ciB0 = pxB0 + 6*(pxB0/22) + 87;
        int ciB1 = pxB1 + 6*(pxB1/22) + 87;

        float tot[2][4][4];
#pragma unroll
        for (int p = 0; p < 2; p++)
#pragma unroll
            for (int nt = 0; nt < 4; nt++)
#pragma unroll
                for (int r = 0; r < 4; r++) tot[p][nt][r] = 0.f;

        for (int cv = 0; cv < 3; cv++) {
            int dil = cv + 1;
            __syncthreads();
            const float* src = cws[cv] + (size_t)gch * 32 * 288;
            for (int i = tid; i < 32*9*16; i += 256) {
                int oc = i / 144, rem = i - oc*144;
                int t = rem / 16, w = rem - t*16;
                float w0 = src[oc*288 + (2*w)*9 + t];
                float w1 = src[oc*288 + (2*w + 1)*9 + t];
                swt[t*32*WSTH + oc*WSTH + w] = packh2(w0, w1);
            }
            __syncthreads();

            float acc[2][4][4];
#pragma unroll
            for (int p = 0; p < 2; p++)
#pragma unroll
                for (int nt = 0; nt < 4; nt++)
#pragma unroll
                    for (int r = 0; r < 4; r++) acc[p][nt][r] = 0.f;

            for (int t = 0; t < 9; t++) {
                int sh = (t/3 - 1)*dil*28 + (t%3 - 1)*dil;
                const unsigned* wt = swt + t*32*WSTH;
#pragma unroll
                for (int ks = 0; ks < 2; ks++) {
                    const unsigned* r0 = cx + (ks*8 + qd)*CVSTH + sh;
                    const unsigned* r1 = cx + (ks*8 + qd + 4)*CVSTH + sh;
                    unsigned aA0 = r0[ciA0], aA1 = r0[ciA1];
                    unsigned aA2 = r1[ciA0], aA3 = r1[ciA1];
                    unsigned aB0 = r0[ciB0], aB1 = r0[ciB1];
                    unsigned aB2 = r1[ciB0], aB3 = r1[ciB1];
#pragma unroll
                    for (int nt = 0; nt < 4; nt++) {
                        unsigned b0 = wt[(nt*8 + grp)*WSTH + ks*8 + qd];
                        unsigned b1 = wt[(nt*8 + grp)*WSTH + ks*8 + qd + 4];
                        mma_f16_k16(acc[0][nt][0], acc[0][nt][1], acc[0][nt][2], acc[0][nt][3],
                                    aA0, aA1, aA2, aA3, b0, b1);
                        mma_f16_k16(acc[1][nt][0], acc[1][nt][1], acc[1][nt][2], acc[1][nt][3],
                                    aB0, aB1, aB2, aB3, b0, b1);
                    }
                }
            }
#pragma unroll
            for (int nt = 0; nt < 4; nt++) {
                float bi0 = cbs[cv][gch*32 + nt*8 + 2*qd];
                float bi1 = cbs[cv][gch*32 + nt*8 + 2*qd + 1];
#pragma unroll
                for (int p = 0; p < 2; p++) {
                    tot[p][nt][0] += fmaxf(acc[p][nt][0] + bi0, 0.f);
                    tot[p][nt][1] += fmaxf(acc[p][nt][1] + bi1, 0.f);
                    tot[p][nt][2] += fmaxf(acc[p][nt][2] + bi0, 0.f);
                    tot[p][nt][3] += fmaxf(acc[p][nt][3] + bi1, 0.f);
                }
            }
        }

        float*  ob  = out  + (size_t)b * SSEQ * DDIM;
        __half* obh = g_hh + (size_t)b * SSEQ * DDIM;
#pragma unroll
        for (int p = 0; p < 2; p++) {
            int px0 = (tA + 8*p)*16 + grp;
            int px1 = px0 + 8;
#pragma unroll
            for (int nt = 0; nt < 4; nt++) {
                int ch = gch*32 + nt*8 + 2*qd;
                if (px0 < SSEQ) {
                    float r0 = hb[(size_t)px0*DDIM + ch];
                    float r1 = hb[(size_t)px0*DDIM + ch + 1];
                    float w0 = 0.5f*(r0 + tot[p][nt][0]);
                    float w1 = 0.5f*(r1 + tot[p][nt][1]);
                    *(float2*)(ob + (size_t)px0*DDIM + ch) = make_float2(w0, w1);
                    *(unsigned*)(obh + (size_t)px0*DDIM + ch) = packh2(w0, w1);
                }
                if (px1 < SSEQ) {
                    float r2 = hb[(size_t)px1*DDIM + ch];
                    float r3 = hb[(size_t)px1*DDIM + ch + 1];
                    float w2 = 0.5f*(r2 + tot[p][nt][2]);
                    float w3 = 0.5f*(r3 + tot[p][nt][3]);
                    *(float2*)(ob + (size_t)px1*DDIM + ch) = make_float2(w2, w3);
                    *(unsigned*)(obh + (size_t)px1*DDIM + ch) = packh2(w2, w3);
                }
            }
        }
        __syncthreads();
    }
}

// ------------------------------ launcher ------------------------------
extern "C" void kernel_launch(void* const* d_in, const int* in_sizes, int n_in,
                              void* d_out, int out_size)
{
    const int* x    = (const int*)d_in[0];
    const float* ev   = (const float*)d_in[2];
    const float* px   = (const float*)d_in[3];
    const float* py   = (const float*)d_in[4];
    const float* st   = (const float*)d_in[5];
    const int* tkx = (const int*)d_in[6];
    const int* tky = (const int*)d_in[7];
    const int* tks = (const int*)d_in[8];
    const float* abias = (const float*)d_in[9];
    const float* Wqkv = (const float*)d_in[10];
    const float* bqkv = (const float*)d_in[11];
    const float* Wo   = (const float*)d_in[12];
    const float* bo   = (const float*)d_in[13];
    const float* W1   = (const float*)d_in[14];
    const float* b1   = (const float*)d_in[15];
    const float* W2   = (const float*)d_in[16];
    const float* b2   = (const float*)d_in[17];
    const float* ln1s = (const float*)d_in[18];
    const float* ln1b = (const float*)d_in[19];
    const float* ln2s = (const float*)d_in[20];
    const float* ln2b = (const float*)d_in[21];
    const float* cw1  = (const float*)d_in[22];
    const float* cb1  = (const float*)d_in[23];
    const float* cw2  = (const float*)d_in[24];
    const float* cb2  = (const float*)d_in[25];
    const float* cw3  = (const float*)d_in[26];
    const float* cb3  = (const float*)d_in[27];
    float* out = (float*)d_out;

    float *hP, *t2P;
    __half *hhP, *qkvP, *t1P, *whP;
    cudaGetSymbolAddress((void**)&hP,   g_h);
    cudaGetSymbolAddress((void**)&hhP,  g_hh);
    cudaGetSymbolAddress((void**)&qkvP, g_qkv);
    cudaGetSymbolAddress((void**)&t1P,  g_t1);
    cudaGetSymbolAddress((void**)&t2P,  g_t2);
    cudaGetSymbolAddress((void**)&whP,  g_wh);

    cudaFuncSetAttribute(k_attn, cudaFuncAttributeMaxDynamicSharedMemorySize, ATTN_SMEM);
    cudaFuncSetAttribute(k_conv, cudaFuncAttributeMaxDynamicSharedMemorySize, CONV_SMEM);
    cudaFuncSetAttribute(k_gemm_h, cudaFuncAttributeMaxDynamicSharedMemorySize, GEMM_SMEM);

    // convert all weights to fp16 once
    k_cvt<<<(6*768*256 + 255)/256, 256>>>(Wqkv, whP + WH_QKV, 6*768*256);
    k_cvt<<<(6*256*256 + 255)/256, 256>>>(Wo,   whP + WH_O,   6*256*256);
    k_cvt<<<(6*512*256 + 255)/256, 256>>>(W1,   whP + WH_1,   6*512*256);
    k_cvt<<<(6*256*512 + 255)/256, 256>>>(W2,   whP + WH_2,   6*256*512);

    k_embed<<<BS_, 256>>>(x, ev, px, py, st, tkx, tky, tks);

    for (int l = 0; l < LNUM; l++) {
        k_gemm_h<<<dim3(6, 220), 256, GEMM_SMEM>>>(hhP, whP + WH_QKV + (size_t)l*768*256,
                                                   bqkv + l*768, (float*)qkvP,
                                                   BS_, 768, 256, 0, 1);
        k_attn<<<BB*HN, 224, ATTN_SMEM>>>(abias);
        k_gemm_h<<<dim3(2, 220), 256, GEMM_SMEM>>>(t1P, whP + WH_O + (size_t)l*256*256,
                                                   bo + l*256, t2P,
                                                   BS_, 256, 256, 0, 0);
        k_ln<<<BS_/8, 256>>>(t2P, ln1s + l*256, ln1b + l*256);
        k_gemm_h<<<dim3(4, 220), 256, GEMM_SMEM>>>(hhP, whP + WH_1 + (size_t)l*512*256,
                                                   b1 + l*512, (float*)t1P,
                                                   BS_, 512, 256, 1, 1);
        k_gemm_h<<<dim3(2, 220), 256, GEMM_SMEM>>>(t1P, whP + WH_2 + (size_t)l*256*512,
                                                   b2 + l*256, t2P,
                                                   BS_, 256, 512, 0, 0);
        k_ln<<<BS_/8, 256>>>(t2P, ln2s + l*256, ln2b + l*256);
        float* cout = (l == LNUM-1) ? out : hP;
        k_conv<<<BB*HN, 256, CONV_SMEM>>>(cw1 + (size_t)l*256*288, cb1 + l*256,
                                          cw2 + (size_t)l*256*288, cb2 + l*256,
                                          cw3 + (size_t)l*256*288, cb3 + l*256,
                                          cout);
    }
}